// round 17
// baseline (speedup 1.0000x reference)
#include <cuda_runtime.h>

#define WID 1024
#define HEI 1024
#define CH  3
#define KR  10
#define BS  128
#define PXT 4
#define SPAN (BS*PXT)        // 512 pixels per block

__device__ __forceinline__ float f4get(const float4 (&v)[7], int m) {
    const float4 f = v[m >> 2];
    switch (m & 3) {
        case 0:  return f.x;
        case 1:  return f.y;
        case 2:  return f.z;
        default: return f.w;
    }
}

__global__ __launch_bounds__(BS, 7) void gauss_h4_kernel(
    const float* __restrict__ x,
    const float* __restrict__ sigma,
    float* __restrict__ out)
{
    const int y   = blockIdx.y;
    const int x0  = blockIdx.x * SPAN;
    const int tid = threadIdx.x;
    const int px  = x0 + 4 * tid;          // first of 4 pixels owned by this thread

    // ---- weight pre-pass (channel-independent): t, t2, hs, inv_norm per pixel ----
    const float4 sg4 = *reinterpret_cast<const float4*>(sigma + y * WID + px);
    const float sgs[4] = { sg4.x, sg4.y, sg4.z, sg4.w };

    float tk[4], t2k[4], hsk[4], invk[4];
    #pragma unroll
    for (int k = 0; k < 4; ++k) {
        const float sig = sgs[k];
        const float t   = __expf(__fdividef(-0.5f, sig * sig));
        const float hs  = ceilf(2.0f * sig);
        const float t2  = t * t;
        float w = 1.0f, u = t, norm = 1.0f;
        #pragma unroll
        for (int i = 1; i <= KR; ++i) {
            w *= u;
            u *= t2;
            norm += ((float)i <= hs) ? 2.0f * w : 0.0f;
        }
        tk[k]   = t;
        t2k[k]  = t2;
        hsk[k]  = hs;
        invk[k] = __fdividef(1.0f, norm);
    }

    // window covers floats [px-12, px+15] (28 floats, 7 aligned float4s);
    // taps need [px-10, px+3+10] = [px-10, px+13] — inside the window.
    const bool interior = (px >= 12) && (px <= WID - 16);

    float* op = out + y * WID + px;
    #pragma unroll
    for (int c = 0; c < CH; ++c) {
        const float* rc = x + (c * HEI + y) * WID;

        float4 wv[7];
        if (interior) {
            const float4* wp = reinterpret_cast<const float4*>(rc + px - 12);
            #pragma unroll
            for (int j = 0; j < 7; ++j) wv[j] = wp[j];
        } else {
            float tmp[28];
            #pragma unroll
            for (int m = 0; m < 28; ++m) {
                int g = px - 12 + m;
                g = min(max(g, 0), WID - 1);
                tmp[m] = rc[g];
            }
            #pragma unroll
            for (int j = 0; j < 7; ++j) {
                wv[j].x = tmp[4*j+0]; wv[j].y = tmp[4*j+1];
                wv[j].z = tmp[4*j+2]; wv[j].w = tmp[4*j+3];
            }
        }

        float accf[4];
        #pragma unroll
        for (int k = 0; k < 4; ++k) {
            // pixel px+k -> window-local center index k+12
            float w = 1.0f, u = tk[k];
            float acc = f4get(wv, k + 12);          // center weight = 1
            const float t2 = t2k[k];
            const float hs = hsk[k];
            #pragma unroll
            for (int i = 1; i <= KR; ++i) {
                w *= u;                              // w = t^(i*i)
                u *= t2;                             // u = t^(2i+1)
                const float wi = ((float)i <= hs) ? w : 0.0f;
                acc += wi * (f4get(wv, k + 12 - i) + f4get(wv, k + 12 + i));
            }
            accf[k] = acc * invk[k];
        }
        float4 r;
        r.x = accf[0]; r.y = accf[1]; r.z = accf[2]; r.w = accf[3];
        *reinterpret_cast<float4*>(op + c * HEI * WID) = r;
    }
}

extern "C" void kernel_launch(void* const* d_in, const int* in_sizes, int n_in,
                              void* d_out, int out_size)
{
    const float* x     = (const float*)d_in[0];
    const float* sigma = (const float*)d_in[1];
    float* out         = (float*)d_out;

    dim3 grid(WID / SPAN, HEI);
    gauss_h4_kernel<<<grid, BS>>>(x, sigma, out);
}